// round 3
// baseline (speedup 1.0000x reference)
#include <cuda_runtime.h>

#define N_NODES 100000
#define N_EDGES 600000
#define N_GRAPHS 512
#define DIM 128
#define N_LAYERS 3
#define BN_EPS 1e-5f
#define NB_SCAN ((N_NODES + 511) / 512)   // 196

// ---------------- scratch (device globals; no allocation allowed) ----------
__device__ __align__(16) float g_AGG[(size_t)N_NODES * DIM];
__device__ __align__(16) float g_T[(size_t)N_NODES * DIM];
__device__ float g_S1[DIM], g_Q1[DIM], g_S2[DIM], g_Q2[DIM];
__device__ float g_SC1[DIM], g_SH1[DIM], g_SC2[DIM], g_SH2[DIM];
__device__ int g_deg[N_NODES];
__device__ int g_rowstart[N_NODES];
__device__ int g_cursor[N_NODES];
__device__ int g_csr_src[N_EDGES];
__device__ int g_part[NB_SCAN];
__device__ int g_gstart[N_GRAPHS + 1];

// ---------------- CSR build -------------------------------------------------
__global__ void deg_zero_kernel() {
    int i = blockIdx.x * blockDim.x + threadIdx.x;
    if (i < N_NODES) g_deg[i] = 0;
}

__global__ void deg_count_kernel(const int* __restrict__ dst) {
    int e = blockIdx.x * blockDim.x + threadIdx.x;
    if (e < N_EDGES) atomicAdd(&g_deg[dst[e]], 1);
}

__global__ void scan_block_kernel() {
    __shared__ int sm[512];
    int t = threadIdx.x;
    int i = blockIdx.x * 512 + t;
    int v = (i < N_NODES) ? g_deg[i] : 0;
    sm[t] = v;
    __syncthreads();
#pragma unroll
    for (int off = 1; off < 512; off <<= 1) {
        int x = (t >= off) ? sm[t - off] : 0;
        __syncthreads();
        sm[t] += x;
        __syncthreads();
    }
    if (i < N_NODES) g_rowstart[i] = sm[t] - v;   // exclusive, block-local
    if (t == 511) g_part[blockIdx.x] = sm[511];
}

__global__ void scan_part_kernel() {
    if (threadIdx.x == 0) {
        int acc = 0;
        for (int b = 0; b < NB_SCAN; b++) {
            int x = g_part[b];
            g_part[b] = acc;
            acc += x;
        }
    }
}

__global__ void scan_add_kernel() {
    int i = blockIdx.x * blockDim.x + threadIdx.x;
    if (i < N_NODES) {
        int rs = g_rowstart[i] + g_part[i >> 9];
        g_rowstart[i] = rs;
        g_cursor[i] = rs;
    }
}

__global__ void fill_csr_kernel(const int* __restrict__ src,
                                const int* __restrict__ dst) {
    int e = blockIdx.x * blockDim.x + threadIdx.x;
    if (e < N_EDGES) {
        int pos = atomicAdd(&g_cursor[dst[e]], 1);
        g_csr_src[pos] = src[e];
    }
}

// segment starts for sorted batch array
__global__ void seg_bounds_kernel(const int* __restrict__ batch) {
    int n = blockIdx.x * blockDim.x + threadIdx.x;
    if (n > N_NODES) return;
    int prev = (n == 0) ? -1 : batch[n - 1];
    int cur = (n == N_NODES) ? N_GRAPHS : batch[n];
    for (int g = prev + 1; g <= cur; g++) g_gstart[g] = n;
}

// ---------------- GIN aggregate: AGG[n] = Hin[n] + sum_{nbr} Hin[nbr] ------
__global__ void gather_kernel(const float* __restrict__ Hin) {
    int gtid = blockIdx.x * blockDim.x + threadIdx.x;
    int node = gtid >> 5;
    int lane = gtid & 31;
    if (node >= N_NODES) return;
    int beg = g_rowstart[node];
    int d = g_deg[node];
    float4 acc = reinterpret_cast<const float4*>(Hin)[node * 32 + lane];
    int j = 0;
    for (; j + 2 <= d; j += 2) {
        int s0 = __ldg(&g_csr_src[beg + j]);
        int s1 = __ldg(&g_csr_src[beg + j + 1]);
        float4 v0 = reinterpret_cast<const float4*>(Hin)[s0 * 32 + lane];
        float4 v1 = reinterpret_cast<const float4*>(Hin)[s1 * 32 + lane];
        acc.x += v0.x + v1.x; acc.y += v0.y + v1.y;
        acc.z += v0.z + v1.z; acc.w += v0.w + v1.w;
    }
    if (j < d) {
        int s0 = __ldg(&g_csr_src[beg + j]);
        float4 v0 = reinterpret_cast<const float4*>(Hin)[s0 * 32 + lane];
        acc.x += v0.x; acc.y += v0.y; acc.z += v0.z; acc.w += v0.w;
    }
    reinterpret_cast<float4*>(g_AGG)[node * 32 + lane] = acc;
}

// ---------------- GEMM + column-stats (R1 proven scalar-FFMA kernel) -------
// PHASE 1: T   = AGG @ W + b        (col stats -> S1/Q1)
// PHASE 2: AGG = BN1(T) @ W + b     (affine on A-load; col stats -> S2/Q2)
template <int PHASE>
__global__ void __launch_bounds__(256) gemm_bn_kernel(const float* __restrict__ W,
                                                      const float* __restrict__ bias) {
    const float* A   = (PHASE == 1) ? g_AGG : g_T;
    float*       Out = (PHASE == 1) ? g_T : g_AGG;
    float*       Sg  = (PHASE == 1) ? g_S1 : g_S2;
    float*       Qg  = (PHASE == 1) ? g_Q1 : g_Q2;

    __shared__ float Ws[32 * DIM];   // one K-chunk of W: [kk][n]
    __shared__ float As[64 * 32];    // A tile chunk:     [row][kk]
    __shared__ float sS[DIM], sQ[DIM];
    __shared__ float sScl[DIM], sShf[DIM];

    int tid = threadIdx.x;
    int tx = tid & 31;         // column group: cols [4*tx, 4*tx+4)
    int ty = tid >> 5;         // row group:    rows [8*ty, 8*ty+8)
    int row0 = blockIdx.x * 64;

    if (tid < DIM) {
        sS[tid] = 0.f; sQ[tid] = 0.f;
        if (PHASE == 2) { sScl[tid] = g_SC1[tid]; sShf[tid] = g_SH1[tid]; }
    }

    float4 bv = reinterpret_cast<const float4*>(bias)[tx];
    float acc[8][4];
#pragma unroll
    for (int r = 0; r < 8; r++) {
        acc[r][0] = bv.x; acc[r][1] = bv.y; acc[r][2] = bv.z; acc[r][3] = bv.w;
    }

    for (int kc = 0; kc < 4; kc++) {
        __syncthreads();
#pragma unroll
        for (int i = 0; i < 4; i++) {
            int idx = tid + i * 256;
            reinterpret_cast<float4*>(Ws)[idx] =
                reinterpret_cast<const float4*>(W)[kc * 1024 + idx];
        }
#pragma unroll
        for (int i = 0; i < 2; i++) {
            int idx = tid + i * 256;
            int r = idx >> 3, kq = idx & 7;
            int grow = row0 + r;
            float4 v = make_float4(0.f, 0.f, 0.f, 0.f);
            if (grow < N_NODES)
                v = reinterpret_cast<const float4*>(A)[grow * 32 + kc * 8 + kq];
            if (PHASE == 2) {
                int kb = kc * 32 + kq * 4;
                v.x = fmaf(v.x, sScl[kb + 0], sShf[kb + 0]);
                v.y = fmaf(v.y, sScl[kb + 1], sShf[kb + 1]);
                v.z = fmaf(v.z, sScl[kb + 2], sShf[kb + 2]);
                v.w = fmaf(v.w, sScl[kb + 3], sShf[kb + 3]);
            }
            reinterpret_cast<float4*>(As)[idx] = v;
        }
        __syncthreads();
#pragma unroll 8
        for (int kk = 0; kk < 32; kk++) {
            float4 w4 = reinterpret_cast<float4*>(Ws)[kk * 32 + tx];
            float a_[8];
#pragma unroll
            for (int r = 0; r < 8; r++) a_[r] = As[(ty * 8 + r) * 32 + kk];
#pragma unroll
            for (int r = 0; r < 8; r++) {
                acc[r][0] = fmaf(a_[r], w4.x, acc[r][0]);
                acc[r][1] = fmaf(a_[r], w4.y, acc[r][1]);
                acc[r][2] = fmaf(a_[r], w4.z, acc[r][2]);
                acc[r][3] = fmaf(a_[r], w4.w, acc[r][3]);
            }
        }
    }

    float s[4] = {0.f, 0.f, 0.f, 0.f}, q[4] = {0.f, 0.f, 0.f, 0.f};
#pragma unroll
    for (int r = 0; r < 8; r++) {
        int grow = row0 + ty * 8 + r;
        if (grow < N_NODES) {
            float4 o = make_float4(acc[r][0], acc[r][1], acc[r][2], acc[r][3]);
            reinterpret_cast<float4*>(Out)[grow * 32 + tx] = o;
#pragma unroll
            for (int c = 0; c < 4; c++) { s[c] += acc[r][c]; q[c] += acc[r][c] * acc[r][c]; }
        }
    }
#pragma unroll
    for (int c = 0; c < 4; c++) {
        atomicAdd(&sS[tx * 4 + c], s[c]);
        atomicAdd(&sQ[tx * 4 + c], q[c]);
    }
    __syncthreads();
    if (tid < DIM) { atomicAdd(&Sg[tid], sS[tid]); atomicAdd(&Qg[tid], sQ[tid]); }
}

// BN1 -> scale/shift (self-zeroing for next layer / next graph replay)
__global__ void stats1_kernel(const float* __restrict__ g, const float* __restrict__ bt) {
    int t = threadIdx.x;
    const float invN = 1.0f / (float)N_NODES;
    float m = g_S1[t] * invN;
    float v = fmaxf(g_Q1[t] * invN - m * m, 0.f);
    g_S1[t] = 0.f; g_Q1[t] = 0.f;
    float r = rsqrtf(v + BN_EPS);
    float sc = r * g[t];
    g_SC1[t] = sc;
    g_SH1[t] = bt[t] - m * sc;
}

// BN2 folded with BN3 (outer): BN3(BN2(x)) = (x - m2) * total + bo
__global__ void stats2_kernel(const float* __restrict__ g2,
                              const float* __restrict__ go,
                              const float* __restrict__ bo) {
    int t = threadIdx.x;
    const float invN = 1.0f / (float)N_NODES;
    float m = g_S2[t] * invN;
    float v = fmaxf(g_Q2[t] * invN - m * m, 0.f);
    g_S2[t] = 0.f; g_Q2[t] = 0.f;
    float r2 = rsqrtf(v + BN_EPS);
    float gg = g2[t];
    float vy = gg * gg * v * r2 * r2;            // exact var of BN2 output
    float sc3 = rsqrtf(vy + BN_EPS) * go[t];
    float total = r2 * gg * sc3;
    g_SC2[t] = total;
    g_SH2[t] = bo[t] - m * total;
}

// H = relu(AGG * sc2 + sh2)
__global__ void apply_relu_kernel(float* __restrict__ H) {
    int i = blockIdx.x * blockDim.x + threadIdx.x;
    if (i >= N_NODES * (DIM / 4)) return;
    int k = (i & 31) * 4;
    float4 v = reinterpret_cast<float4*>(g_AGG)[i];
    v.x = fmaxf(fmaf(v.x, g_SC2[k + 0], g_SH2[k + 0]), 0.f);
    v.y = fmaxf(fmaf(v.y, g_SC2[k + 1], g_SH2[k + 1]), 0.f);
    v.z = fmaxf(fmaf(v.z, g_SC2[k + 2], g_SH2[k + 2]), 0.f);
    v.w = fmaxf(fmaf(v.w, g_SC2[k + 3], g_SH2[k + 3]), 0.f);
    reinterpret_cast<float4*>(H)[i] = v;
}

// ---------------- pooling + classifier (contiguous segments, no atomics) ---
__global__ void graph_fc_kernel(const float* __restrict__ H,
                                const float* __restrict__ fcW,
                                const float* __restrict__ fcb,
                                float* __restrict__ Gout,
                                float* __restrict__ Cout) {
    int g = blockIdx.x;
    int t = threadIdx.x;   // 128
    int beg = g_gstart[g], end = g_gstart[g + 1];
    float s = 0.f;
    for (int r = beg; r < end; r++) s += H[r * DIM + t];
    float cnt = fmaxf((float)(end - beg), 1.0f);
    float ge = s / cnt;
    Gout[g * DIM + t] = ge;
    __shared__ float r0[DIM], r1[DIM];
    r0[t] = ge * fcW[t * 2 + 0];
    r1[t] = ge * fcW[t * 2 + 1];
    __syncthreads();
    for (int sh = 64; sh > 0; sh >>= 1) {
        if (t < sh) { r0[t] += r0[t + sh]; r1[t] += r1[t + sh]; }
        __syncthreads();
    }
    if (t == 0) {
        Cout[g * 2 + 0] = r0[0] + fcb[0];
        Cout[g * 2 + 1] = r1[0] + fcb[1];
    }
}

// ---------------- launcher ---------------------------------------------------
extern "C" void kernel_launch(void* const* d_in, const int* in_sizes, int n_in,
                              void* d_out, int out_size) {
    const float* x     = (const float*)d_in[0];
    const int*   ei    = (const int*)d_in[1];
    const int*   batch = (const int*)d_in[2];
    const float* W1    = (const float*)d_in[3];
    const float* b1    = (const float*)d_in[4];
    const float* g1    = (const float*)d_in[5];
    const float* bt1   = (const float*)d_in[6];
    const float* W2    = (const float*)d_in[7];
    const float* b2    = (const float*)d_in[8];
    const float* g2    = (const float*)d_in[9];
    // d_in[10] (bt2) cancels analytically in BN2∘BN3
    const float* go    = (const float*)d_in[11];
    const float* bo    = (const float*)d_in[12];
    const float* fcW   = (const float*)d_in[13];
    const float* fcb   = (const float*)d_in[14];

    float* out  = (float*)d_out;
    float* Hout = out;                               // node embeddings
    float* Gout = out + (size_t)N_NODES * DIM;       // graph embedding
    float* Cout = Gout + (size_t)N_GRAPHS * DIM;     // classifier output

    const int* src = ei;
    const int* dst = ei + N_EDGES;

    const int nNodeBlocks   = (N_NODES + 255) / 256;
    const int nEdgeBlocks   = (N_EDGES + 255) / 256;
    const int nGatherBlocks = (N_NODES * 32 + 255) / 256;        // 12500
    const int nCopyBlocks   = (N_NODES * (DIM / 4)) / 256;       // 12500
    const int nGemmBlocks   = (N_NODES + 63) / 64;               // 1563

    // ---- CSR build (once per replay) ----
    deg_zero_kernel<<<nNodeBlocks, 256>>>();
    deg_count_kernel<<<nEdgeBlocks, 256>>>(dst);
    scan_block_kernel<<<NB_SCAN, 512>>>();
    scan_part_kernel<<<1, 32>>>();
    scan_add_kernel<<<nNodeBlocks, 256>>>();
    fill_csr_kernel<<<nEdgeBlocks, 256>>>(src, dst);
    seg_bounds_kernel<<<(N_NODES + 256) / 256, 256>>>(batch);

    for (int i = 0; i < N_LAYERS; i++) {
        const float* Hin = (i == 0) ? x : Hout;
        gather_kernel<<<nGatherBlocks, 256>>>(Hin);
        gemm_bn_kernel<1><<<nGemmBlocks, 256>>>(W1 + (size_t)i * DIM * DIM, b1 + i * DIM);
        stats1_kernel<<<1, 128>>>(g1 + i * DIM, bt1 + i * DIM);
        gemm_bn_kernel<2><<<nGemmBlocks, 256>>>(W2 + (size_t)i * DIM * DIM, b2 + i * DIM);
        stats2_kernel<<<1, 128>>>(g2 + i * DIM, go + i * DIM, bo + i * DIM);
        apply_relu_kernel<<<nCopyBlocks, 256>>>(Hout);
    }

    graph_fc_kernel<<<N_GRAPHS, 128>>>(Hout, fcW, fcb, Gout, Cout);
}

// round 5
// speedup vs baseline: 1.7713x; 1.7713x over previous
#include <cuda_runtime.h>
#include <cuda_bf16.h>
#include <cstdint>

#define N_NODES 100000
#define N_EDGES 600000
#define N_GRAPHS 512
#define DIM 128
#define N_LAYERS 3
#define BN_EPS 1e-5f

// ---------------- scratch (device globals; no allocation allowed) ----------
__device__ __align__(16) float g_AGG[(size_t)N_NODES * DIM];
__device__ __align__(16) float g_T[(size_t)N_NODES * DIM];
__device__ float g_S1[DIM], g_Q1[DIM], g_S2[DIM], g_Q2[DIM];
__device__ float g_SC1[DIM], g_SH1[DIM], g_SC2[DIM], g_SH2[DIM];
__device__ int g_gstart[N_GRAPHS + 1];
// W in mma.sync B-fragment layout, bf16 split: [mat][kb 8][nb 16][lane 32][reg 2]
__device__ __align__(16) uint32_t g_Whi[6 * 8192];
__device__ __align__(16) uint32_t g_Wlo[6 * 8192];

// ---------------- helpers ----------------------------------------------------
__device__ __forceinline__ uint32_t pack_bf16x2(float f0, float f1) {
    __nv_bfloat162 h = __floats2bfloat162_rn(f0, f1);
    return *reinterpret_cast<uint32_t*>(&h);
}
__device__ __forceinline__ void split2(float2 v, uint32_t& hi, uint32_t& lo) {
    __nv_bfloat16 h0 = __float2bfloat16_rn(v.x);
    __nv_bfloat16 h1 = __float2bfloat16_rn(v.y);
    float l0 = v.x - __bfloat162float(h0);
    float l1 = v.y - __bfloat162float(h1);
    __nv_bfloat162 hp; hp.x = h0; hp.y = h1;
    hi = *reinterpret_cast<uint32_t*>(&hp);
    lo = pack_bf16x2(l0, l1);
}
__device__ __forceinline__ void mma_bf16(float c[4], const uint32_t a[4], uint32_t b0, uint32_t b1) {
    asm volatile(
        "mma.sync.aligned.m16n8k16.row.col.f32.bf16.bf16.f32 "
        "{%0,%1,%2,%3}, {%4,%5,%6,%7}, {%8,%9}, {%0,%1,%2,%3};"
        : "+f"(c[0]), "+f"(c[1]), "+f"(c[2]), "+f"(c[3])
        : "r"(a[0]), "r"(a[1]), "r"(a[2]), "r"(a[3]), "r"(b0), "r"(b1));
}

// ---------------- W prep: split + fragment layout ----------------------------
// frag element: k = kb*16 + (lane%4)*2 + r*8 + {0,1}, n = nb*8 + lane/4
__global__ void wprep_kernel(const float* __restrict__ W1, const float* __restrict__ W2) {
    int idx = blockIdx.x * blockDim.x + threadIdx.x;   // 0 .. 6*8192-1
    if (idx >= 6 * 8192) return;
    int mat = idx >> 13;
    int e = idx & 8191;
    int r = e & 1;
    int lane = (e >> 1) & 31;
    int nb = (e >> 6) & 15;
    int kb = e >> 10;
    int k0 = kb * 16 + (lane & 3) * 2 + r * 8;
    int n = nb * 8 + (lane >> 2);
    const float* W = (mat < 3) ? (W1 + (size_t)mat * 16384)
                               : (W2 + (size_t)(mat - 3) * 16384);
    float w0 = W[k0 * 128 + n];
    float w1 = W[(k0 + 1) * 128 + n];
    uint32_t hi, lo;
    split2(make_float2(w0, w1), hi, lo);
    g_Whi[idx] = hi;
    g_Wlo[idx] = lo;
}

// ---------------- aggregation (R1 proven path) -------------------------------
__global__ void copy_to_agg_kernel(const float* __restrict__ H) {
    int i = blockIdx.x * blockDim.x + threadIdx.x;
    if (i < N_NODES * (DIM / 4))
        reinterpret_cast<float4*>(g_AGG)[i] = reinterpret_cast<const float4*>(H)[i];
}

__global__ void scatter_add_kernel(const float* __restrict__ H,
                                   const int* __restrict__ src,
                                   const int* __restrict__ dst) {
    int idx = blockIdx.x * blockDim.x + threadIdx.x;
    if (idx >= N_EDGES * (DIM / 4)) return;
    int e = idx >> 5;
    int j = idx & 31;
    int s = __ldg(&src[e]);
    int d = __ldg(&dst[e]);
    float4 v = reinterpret_cast<const float4*>(H)[s * 32 + j];
    atomicAdd(reinterpret_cast<float4*>(g_AGG) + d * 32 + j, v);
}

// ---------------- HMMA GEMM + column stats -----------------------------------
// PHASE 1: T   = AGG @ W + b    (stats -> S1/Q1)
// PHASE 2: AGG = BN1(T) @ W + b (affine on A-load; stats -> S2/Q2)
// Block: 128 rows x 128 cols, 8 warps; warp w -> rows [16w,16w+16).
#define SMB_BHI 0
#define SMB_BLO 32768
#define SMB_BIAS 65536
#define SMB_SCL 66048
#define SMB_SHF 66560
#define SMB_SS 67072
#define SMB_SQ 67584
#define SMB_TOTAL 68096

template <int PHASE>
__global__ void __launch_bounds__(256) gemm_mma_kernel(int mat, const float* __restrict__ bias) {
    const float* A   = (PHASE == 1) ? g_AGG : g_T;
    float*       Out = (PHASE == 1) ? g_T : g_AGG;
    float*       Sg  = (PHASE == 1) ? g_S1 : g_S2;
    float*       Qg  = (PHASE == 1) ? g_Q1 : g_Q2;

    extern __shared__ __align__(16) char smem[];
    uint32_t* sBhi = reinterpret_cast<uint32_t*>(smem + SMB_BHI);
    uint32_t* sBlo = reinterpret_cast<uint32_t*>(smem + SMB_BLO);
    float* sBias = reinterpret_cast<float*>(smem + SMB_BIAS);
    float* sScl  = reinterpret_cast<float*>(smem + SMB_SCL);
    float* sShf  = reinterpret_cast<float*>(smem + SMB_SHF);
    float* sS    = reinterpret_cast<float*>(smem + SMB_SS);
    float* sQ    = reinterpret_cast<float*>(smem + SMB_SQ);

    const int tid = threadIdx.x;
    const int wid = tid >> 5;
    const int lane = tid & 31;
    const int qrow = lane >> 2;         // 0..7
    const int qk = (lane & 3) * 2;      // 0,2,4,6
    const int row0 = blockIdx.x * 128;

    // load B fragments (pre-split, pre-laid-out) into smem
    {
        const float4* wh = reinterpret_cast<const float4*>(g_Whi + mat * 8192);
        const float4* wl = reinterpret_cast<const float4*>(g_Wlo + mat * 8192);
        float4* bh = reinterpret_cast<float4*>(sBhi);
        float4* bl = reinterpret_cast<float4*>(sBlo);
#pragma unroll
        for (int i = 0; i < 8; i++) {
            int idx = tid + i * 256;
            bh[idx] = wh[idx];
            bl[idx] = wl[idx];
        }
    }
    if (tid < DIM) {
        sBias[tid] = bias[tid];
        sS[tid] = 0.f; sQ[tid] = 0.f;
        if (PHASE == 2) { sScl[tid] = g_SC1[tid]; sShf[tid] = g_SH1[tid]; }
    }
    __syncthreads();

    const int r0 = row0 + wid * 16 + qrow;
    const int r1 = r0 + 8;
    const bool v0 = (r0 < N_NODES);
    const bool v1 = (r1 < N_NODES);
    const float* a0p = A + (size_t)r0 * DIM;
    const float* a1p = A + (size_t)r1 * DIM;

    float c[16][4];
#pragma unroll
    for (int nb = 0; nb < 16; nb++) {
        c[nb][0] = 0.f; c[nb][1] = 0.f; c[nb][2] = 0.f; c[nb][3] = 0.f;
    }

#pragma unroll
    for (int kb = 0; kb < 8; kb++) {
        const int c0 = kb * 16 + qk;
        float2 x00 = make_float2(0.f, 0.f), x01 = x00, x10 = x00, x11 = x00;
        if (v0) {
            x00 = *reinterpret_cast<const float2*>(a0p + c0);
            x01 = *reinterpret_cast<const float2*>(a0p + c0 + 8);
        }
        if (v1) {
            x10 = *reinterpret_cast<const float2*>(a1p + c0);
            x11 = *reinterpret_cast<const float2*>(a1p + c0 + 8);
        }
        if (PHASE == 2) {
            x00.x = fmaf(x00.x, sScl[c0], sShf[c0]);
            x00.y = fmaf(x00.y, sScl[c0 + 1], sShf[c0 + 1]);
            x01.x = fmaf(x01.x, sScl[c0 + 8], sShf[c0 + 8]);
            x01.y = fmaf(x01.y, sScl[c0 + 9], sShf[c0 + 9]);
            x10.x = fmaf(x10.x, sScl[c0], sShf[c0]);
            x10.y = fmaf(x10.y, sScl[c0 + 1], sShf[c0 + 1]);
            x11.x = fmaf(x11.x, sScl[c0 + 8], sShf[c0 + 8]);
            x11.y = fmaf(x11.y, sScl[c0 + 9], sShf[c0 + 9]);
        }
        uint32_t ahi[4], alo[4];
        split2(x00, ahi[0], alo[0]);
        split2(x10, ahi[1], alo[1]);
        split2(x01, ahi[2], alo[2]);
        split2(x11, ahi[3], alo[3]);

#pragma unroll
        for (int nb = 0; nb < 16; nb++) {
            const int fi = ((kb * 16 + nb) * 32 + lane) * 2;
            const uint2 bh = *reinterpret_cast<const uint2*>(&sBhi[fi]);
            const uint2 bl = *reinterpret_cast<const uint2*>(&sBlo[fi]);
            mma_bf16(c[nb], ahi, bh.x, bh.y);
            mma_bf16(c[nb], ahi, bl.x, bl.y);
            mma_bf16(c[nb], alo, bh.x, bh.y);
        }
    }

    // ---- epilogue: bias + store + column stats ----
#pragma unroll
    for (int nb = 0; nb < 16; nb++) {
        const int cn = nb * 8 + qk;
        const float b0 = sBias[cn], b1 = sBias[cn + 1];
        float o00 = v0 ? (c[nb][0] + b0) : 0.f;
        float o01 = v0 ? (c[nb][1] + b1) : 0.f;
        float o10 = v1 ? (c[nb][2] + b0) : 0.f;
        float o11 = v1 ? (c[nb][3] + b1) : 0.f;
        if (v0) *reinterpret_cast<float2*>(Out + (size_t)r0 * DIM + cn) = make_float2(o00, o01);
        if (v1) *reinterpret_cast<float2*>(Out + (size_t)r1 * DIM + cn) = make_float2(o10, o11);
        float s0 = o00 + o10, s1 = o01 + o11;
        float q0 = o00 * o00 + o10 * o10, q1 = o01 * o01 + o11 * o11;
#pragma unroll
        for (int off = 4; off < 32; off <<= 1) {
            s0 += __shfl_down_sync(0xFFFFFFFF, s0, off);
            s1 += __shfl_down_sync(0xFFFFFFFF, s1, off);
            q0 += __shfl_down_sync(0xFFFFFFFF, q0, off);
            q1 += __shfl_down_sync(0xFFFFFFFF, q1, off);
        }
        if (lane < 4) {
            atomicAdd(&sS[cn], s0);
            atomicAdd(&sS[cn + 1], s1);
            atomicAdd(&sQ[cn], q0);
            atomicAdd(&sQ[cn + 1], q1);
        }
    }
    __syncthreads();
    if (tid < DIM) { atomicAdd(&Sg[tid], sS[tid]); atomicAdd(&Qg[tid], sQ[tid]); }
}

// ---------------- BN folding kernels (self-zeroing) --------------------------
__global__ void stats1_kernel(const float* __restrict__ g, const float* __restrict__ bt) {
    int t = threadIdx.x;
    const float invN = 1.0f / (float)N_NODES;
    float m = g_S1[t] * invN;
    float v = fmaxf(g_Q1[t] * invN - m * m, 0.f);
    g_S1[t] = 0.f; g_Q1[t] = 0.f;
    float r = rsqrtf(v + BN_EPS);
    float sc = r * g[t];
    g_SC1[t] = sc;
    g_SH1[t] = bt[t] - m * sc;
}

__global__ void stats2_kernel(const float* __restrict__ g2,
                              const float* __restrict__ go,
                              const float* __restrict__ bo) {
    int t = threadIdx.x;
    const float invN = 1.0f / (float)N_NODES;
    float m = g_S2[t] * invN;
    float v = fmaxf(g_Q2[t] * invN - m * m, 0.f);
    g_S2[t] = 0.f; g_Q2[t] = 0.f;
    float r2 = rsqrtf(v + BN_EPS);
    float gg = g2[t];
    float vy = gg * gg * v * r2 * r2;            // exact var of BN2 output
    float sc3 = rsqrtf(vy + BN_EPS) * go[t];
    float total = r2 * gg * sc3;
    g_SC2[t] = total;
    g_SH2[t] = bo[t] - m * total;
}

__global__ void apply_relu_kernel(float* __restrict__ H) {
    int i = blockIdx.x * blockDim.x + threadIdx.x;
    if (i >= N_NODES * (DIM / 4)) return;
    int k = (i & 31) * 4;
    float4 v = reinterpret_cast<float4*>(g_AGG)[i];
    v.x = fmaxf(fmaf(v.x, g_SC2[k + 0], g_SH2[k + 0]), 0.f);
    v.y = fmaxf(fmaf(v.y, g_SC2[k + 1], g_SH2[k + 1]), 0.f);
    v.z = fmaxf(fmaf(v.z, g_SC2[k + 2], g_SH2[k + 2]), 0.f);
    v.w = fmaxf(fmaf(v.w, g_SC2[k + 3], g_SH2[k + 3]), 0.f);
    reinterpret_cast<float4*>(H)[i] = v;
}

// ---------------- pooling + classifier ---------------------------------------
__global__ void seg_bounds_kernel(const int* __restrict__ batch) {
    int n = blockIdx.x * blockDim.x + threadIdx.x;
    if (n > N_NODES) return;
    int prev = (n == 0) ? -1 : batch[n - 1];
    int cur = (n == N_NODES) ? N_GRAPHS : batch[n];
    for (int g = prev + 1; g <= cur; g++) g_gstart[g] = n;
}

__global__ void graph_fc_kernel(const float* __restrict__ H,
                                const float* __restrict__ fcW,
                                const float* __restrict__ fcb,
                                float* __restrict__ Gout,
                                float* __restrict__ Cout) {
    int g = blockIdx.x;
    int t = threadIdx.x;
    int beg = g_gstart[g], end = g_gstart[g + 1];
    float s = 0.f;
    for (int r = beg; r < end; r++) s += H[r * DIM + t];
    float cnt = fmaxf((float)(end - beg), 1.0f);
    float ge = s / cnt;
    Gout[g * DIM + t] = ge;
    __shared__ float r0[DIM], r1[DIM];
    r0[t] = ge * fcW[t * 2 + 0];
    r1[t] = ge * fcW[t * 2 + 1];
    __syncthreads();
    for (int sh = 64; sh > 0; sh >>= 1) {
        if (t < sh) { r0[t] += r0[t + sh]; r1[t] += r1[t + sh]; }
        __syncthreads();
    }
    if (t == 0) {
        Cout[g * 2 + 0] = r0[0] + fcb[0];
        Cout[g * 2 + 1] = r1[0] + fcb[1];
    }
}

// ---------------- launcher ---------------------------------------------------
extern "C" void kernel_launch(void* const* d_in, const int* in_sizes, int n_in,
                              void* d_out, int out_size) {
    const float* x     = (const float*)d_in[0];
    const int*   ei    = (const int*)d_in[1];
    const int*   batch = (const int*)d_in[2];
    const float* W1    = (const float*)d_in[3];
    const float* b1    = (const float*)d_in[4];
    const float* g1    = (const float*)d_in[5];
    const float* bt1   = (const float*)d_in[6];
    const float* W2    = (const float*)d_in[7];
    const float* b2    = (const float*)d_in[8];
    const float* g2    = (const float*)d_in[9];
    // d_in[10] (bt2) cancels analytically in BN2∘BN3
    const float* go    = (const float*)d_in[11];
    const float* bo    = (const float*)d_in[12];
    const float* fcW   = (const float*)d_in[13];
    const float* fcb   = (const float*)d_in[14];

    float* out  = (float*)d_out;
    float* Hout = out;
    float* Gout = out + (size_t)N_NODES * DIM;
    float* Cout = Gout + (size_t)N_GRAPHS * DIM;

    const int* src = ei;
    const int* dst = ei + N_EDGES;

    static bool attr_set = false;
    if (!attr_set) {
        cudaFuncSetAttribute(gemm_mma_kernel<1>, cudaFuncAttributeMaxDynamicSharedMemorySize, SMB_TOTAL);
        cudaFuncSetAttribute(gemm_mma_kernel<2>, cudaFuncAttributeMaxDynamicSharedMemorySize, SMB_TOTAL);
        attr_set = true;
    }

    const int nCopyBlocks    = (N_NODES * (DIM / 4)) / 256;      // 12500
    const int nScatterBlocks = (N_EDGES * (DIM / 4)) / 256;      // 75000
    const int nGemmBlocks    = (N_NODES + 127) / 128;            // 782

    wprep_kernel<<<(6 * 8192 + 255) / 256, 256>>>(W1, W2);
    seg_bounds_kernel<<<(N_NODES + 256) / 256, 256>>>(batch);

    for (int i = 0; i < N_LAYERS; i++) {
        const float* Hin = (i == 0) ? x : Hout;
        copy_to_agg_kernel<<<nCopyBlocks, 256>>>(Hin);
        scatter_add_kernel<<<nScatterBlocks, 256>>>(Hin, src, dst);
        gemm_mma_kernel<1><<<nGemmBlocks, 256, SMB_TOTAL>>>(i, b1 + i * DIM);
        stats1_kernel<<<1, 128>>>(g1 + i * DIM, bt1 + i * DIM);
        gemm_mma_kernel<2><<<nGemmBlocks, 256, SMB_TOTAL>>>(i + 3, b2 + i * DIM);
        stats2_kernel<<<1, 128>>>(g2 + i * DIM, go + i * DIM, bo + i * DIM);
        apply_relu_kernel<<<nCopyBlocks, 256>>>(Hout);
    }

    graph_fc_kernel<<<N_GRAPHS, 128>>>(Hout, fcW, fcb, Gout, Cout);
}

// round 6
// speedup vs baseline: 1.9883x; 1.1226x over previous
#include <cuda_runtime.h>
#include <cuda_bf16.h>
#include <cstdint>

#define N_NODES 100000
#define N_EDGES 600000
#define N_GRAPHS 512
#define DIM 128
#define N_LAYERS 3
#define BN_EPS 1e-5f

// ---------------- scratch (device globals; no allocation allowed) ----------
__device__ __align__(16) float g_AGG[(size_t)N_NODES * DIM];
__device__ __align__(16) float g_T[(size_t)N_NODES * DIM];
__device__ float g_S1[DIM], g_Q1[DIM], g_S2[DIM], g_Q2[DIM];
__device__ float g_SC1[DIM], g_SH1[DIM], g_SC2[DIM], g_SH2[DIM];
__device__ int g_gstart[N_GRAPHS + 1];
// W fragments, interleaved {hi0,hi1,lo0,lo1}: [mat][kb 8][nb 16][lane 32][4]
__device__ __align__(16) uint32_t g_Wfrag[6 * 16384];

// ---------------- helpers ----------------------------------------------------
__device__ __forceinline__ uint32_t pack_bf16x2(float f0, float f1) {
    __nv_bfloat162 h = __floats2bfloat162_rn(f0, f1);
    return *reinterpret_cast<uint32_t*>(&h);
}
__device__ __forceinline__ void split2(float2 v, uint32_t& hi, uint32_t& lo) {
    __nv_bfloat16 h0 = __float2bfloat16_rn(v.x);
    __nv_bfloat16 h1 = __float2bfloat16_rn(v.y);
    float l0 = v.x - __bfloat162float(h0);
    float l1 = v.y - __bfloat162float(h1);
    __nv_bfloat162 hp; hp.x = h0; hp.y = h1;
    hi = *reinterpret_cast<uint32_t*>(&hp);
    lo = pack_bf16x2(l0, l1);
}
__device__ __forceinline__ void mma_bf16(float c[4], const uint32_t a[4], uint32_t b0, uint32_t b1) {
    asm volatile(
        "mma.sync.aligned.m16n8k16.row.col.f32.bf16.bf16.f32 "
        "{%0,%1,%2,%3}, {%4,%5,%6,%7}, {%8,%9}, {%0,%1,%2,%3};"
        : "+f"(c[0]), "+f"(c[1]), "+f"(c[2]), "+f"(c[3])
        : "r"(a[0]), "r"(a[1]), "r"(a[2]), "r"(a[3]), "r"(b0), "r"(b1));
}

// ---------------- W prep: split + interleaved fragment layout ----------------
// frag element: k = kb*16 + (lane%4)*2 + r*8 + {0,1}, n = nb*8 + lane/4
__global__ void wprep_kernel(const float* __restrict__ W1, const float* __restrict__ W2) {
    int idx = blockIdx.x * blockDim.x + threadIdx.x;   // 0 .. 6*4096-1 (frag quads)
    if (idx >= 6 * 4096) return;
    int mat = idx >> 12;
    int e = idx & 4095;
    int lane = e & 31;
    int nb = (e >> 5) & 15;
    int kb = e >> 9;
    int n = nb * 8 + (lane >> 2);
    const float* W = (mat < 3) ? (W1 + (size_t)mat * 16384)
                               : (W2 + (size_t)(mat - 3) * 16384);
    uint32_t hi0, lo0, hi1, lo1;
    {
        int k0 = kb * 16 + (lane & 3) * 2;
        split2(make_float2(W[k0 * 128 + n], W[(k0 + 1) * 128 + n]), hi0, lo0);
        int k1 = k0 + 8;
        split2(make_float2(W[k1 * 128 + n], W[(k1 + 1) * 128 + n]), hi1, lo1);
    }
    uint4 q = make_uint4(hi0, hi1, lo0, lo1);
    reinterpret_cast<uint4*>(g_Wfrag)[mat * 4096 + e] = q;
}

// ---------------- aggregation -------------------------------------------------
__global__ void copy_to_agg_kernel(const float* __restrict__ H) {
    int i = blockIdx.x * blockDim.x + threadIdx.x;
    if (i < N_NODES * (DIM / 4))
        reinterpret_cast<float4*>(g_AGG)[i] = reinterpret_cast<const float4*>(H)[i];
}

// AGG[dst] += H[src] — 2 independent edge-chunks per thread for MLP
#define SCATTER_WORK (N_EDGES * 32)          // float4 chunks total
#define SCATTER_HALF (SCATTER_WORK / 2)
__global__ void scatter_add_kernel(const float* __restrict__ H,
                                   const int* __restrict__ src,
                                   const int* __restrict__ dst) {
    int idx = blockIdx.x * blockDim.x + threadIdx.x;
    if (idx >= SCATTER_HALF) return;
    int e0 = idx >> 5;
    int j0 = idx & 31;
    int e1 = (idx + SCATTER_HALF) >> 5;
    int j1 = j0;
    int s0 = __ldg(&src[e0]);
    int d0 = __ldg(&dst[e0]);
    int s1 = __ldg(&src[e1]);
    int d1 = __ldg(&dst[e1]);
    float4 v0 = reinterpret_cast<const float4*>(H)[s0 * 32 + j0];
    float4 v1 = reinterpret_cast<const float4*>(H)[s1 * 32 + j1];
    atomicAdd(reinterpret_cast<float4*>(g_AGG) + d0 * 32 + j0, v0);
    atomicAdd(reinterpret_cast<float4*>(g_AGG) + d1 * 32 + j1, v1);
}

// ---------------- HMMA GEMM + column stats -----------------------------------
// PHASE 1: T   = AGG @ W + b    (stats -> S1/Q1)
// PHASE 2: AGG = BN1(T) @ W + b (affine on A-load; stats -> S2/Q2)
// Block: 128 rows x 128 cols, 8 warps; warp w -> rows [16w,16w+16).
#define SMB_BFRAG 0
#define SMB_BIAS 65536
#define SMB_SCL 66048
#define SMB_SHF 66560
#define SMB_SS 67072
#define SMB_SQ 67584
#define SMB_TOTAL 68096

template <int PHASE>
__global__ void __launch_bounds__(256) gemm_mma_kernel(int mat, const float* __restrict__ bias) {
    const float* A   = (PHASE == 1) ? g_AGG : g_T;
    float*       Out = (PHASE == 1) ? g_T : g_AGG;
    float*       Sg  = (PHASE == 1) ? g_S1 : g_S2;
    float*       Qg  = (PHASE == 1) ? g_Q1 : g_Q2;

    extern __shared__ __align__(16) char smem[];
    uint32_t* sBf  = reinterpret_cast<uint32_t*>(smem + SMB_BFRAG);
    float* sBias = reinterpret_cast<float*>(smem + SMB_BIAS);
    float* sScl  = reinterpret_cast<float*>(smem + SMB_SCL);
    float* sShf  = reinterpret_cast<float*>(smem + SMB_SHF);
    float* sS    = reinterpret_cast<float*>(smem + SMB_SS);
    float* sQ    = reinterpret_cast<float*>(smem + SMB_SQ);

    const int tid = threadIdx.x;
    const int wid = tid >> 5;
    const int lane = tid & 31;
    const int qrow = lane >> 2;
    const int qk = (lane & 3) * 2;
    const int row0 = blockIdx.x * 128;

    {
        const uint4* wf = reinterpret_cast<const uint4*>(g_Wfrag + mat * 16384);
        uint4* bf = reinterpret_cast<uint4*>(sBf);
#pragma unroll
        for (int i = 0; i < 16; i++) {
            int idx = tid + i * 256;
            bf[idx] = wf[idx];
        }
    }
    if (tid < DIM) {
        sBias[tid] = bias[tid];
        sS[tid] = 0.f; sQ[tid] = 0.f;
        if (PHASE == 2) { sScl[tid] = g_SC1[tid]; sShf[tid] = g_SH1[tid]; }
    }
    __syncthreads();

    const int r0 = row0 + wid * 16 + qrow;
    const int r1 = r0 + 8;
    const bool v0 = (r0 < N_NODES);
    const bool v1 = (r1 < N_NODES);
    const float* a0p = A + (size_t)r0 * DIM;
    const float* a1p = A + (size_t)r1 * DIM;

    float c[16][4];
#pragma unroll
    for (int nb = 0; nb < 16; nb++) {
        c[nb][0] = 0.f; c[nb][1] = 0.f; c[nb][2] = 0.f; c[nb][3] = 0.f;
    }

#pragma unroll
    for (int kb = 0; kb < 8; kb++) {
        const int c0 = kb * 16 + qk;
        float2 x00 = make_float2(0.f, 0.f), x01 = x00, x10 = x00, x11 = x00;
        if (v0) {
            x00 = *reinterpret_cast<const float2*>(a0p + c0);
            x01 = *reinterpret_cast<const float2*>(a0p + c0 + 8);
        }
        if (v1) {
            x10 = *reinterpret_cast<const float2*>(a1p + c0);
            x11 = *reinterpret_cast<const float2*>(a1p + c0 + 8);
        }
        if (PHASE == 2) {
            x00.x = fmaf(x00.x, sScl[c0], sShf[c0]);
            x00.y = fmaf(x00.y, sScl[c0 + 1], sShf[c0 + 1]);
            x01.x = fmaf(x01.x, sScl[c0 + 8], sShf[c0 + 8]);
            x01.y = fmaf(x01.y, sScl[c0 + 9], sShf[c0 + 9]);
            x10.x = fmaf(x10.x, sScl[c0], sShf[c0]);
            x10.y = fmaf(x10.y, sScl[c0 + 1], sShf[c0 + 1]);
            x11.x = fmaf(x11.x, sScl[c0 + 8], sShf[c0 + 8]);
            x11.y = fmaf(x11.y, sScl[c0 + 9], sShf[c0 + 9]);
        }
        uint32_t ahi[4], alo[4];
        split2(x00, ahi[0], alo[0]);
        split2(x10, ahi[1], alo[1]);
        split2(x01, ahi[2], alo[2]);
        split2(x11, ahi[3], alo[3]);

#pragma unroll
        for (int nb = 0; nb < 16; nb++) {
            const uint4 b = *reinterpret_cast<const uint4*>(&sBf[((kb * 16 + nb) * 32 + lane) * 4]);
            mma_bf16(c[nb], ahi, b.x, b.y);
            mma_bf16(c[nb], ahi, b.z, b.w);
            mma_bf16(c[nb], alo, b.x, b.y);
        }
    }

    // ---- epilogue: bias + store + column stats ----
#pragma unroll
    for (int nb = 0; nb < 16; nb++) {
        const int cn = nb * 8 + qk;
        const float b0 = sBias[cn], b1 = sBias[cn + 1];
        float o00 = v0 ? (c[nb][0] + b0) : 0.f;
        float o01 = v0 ? (c[nb][1] + b1) : 0.f;
        float o10 = v1 ? (c[nb][2] + b0) : 0.f;
        float o11 = v1 ? (c[nb][3] + b1) : 0.f;
        if (v0) *reinterpret_cast<float2*>(Out + (size_t)r0 * DIM + cn) = make_float2(o00, o01);
        if (v1) *reinterpret_cast<float2*>(Out + (size_t)r1 * DIM + cn) = make_float2(o10, o11);
        float s0 = o00 + o10, s1 = o01 + o11;
        float q0 = o00 * o00 + o10 * o10, q1 = o01 * o01 + o11 * o11;
#pragma unroll
        for (int off = 4; off < 32; off <<= 1) {
            s0 += __shfl_down_sync(0xFFFFFFFF, s0, off);
            s1 += __shfl_down_sync(0xFFFFFFFF, s1, off);
            q0 += __shfl_down_sync(0xFFFFFFFF, q0, off);
            q1 += __shfl_down_sync(0xFFFFFFFF, q1, off);
        }
        if (lane < 4) {
            atomicAdd(&sS[cn], s0);
            atomicAdd(&sS[cn + 1], s1);
            atomicAdd(&sQ[cn], q0);
            atomicAdd(&sQ[cn + 1], q1);
        }
    }
    __syncthreads();
    if (tid < DIM) { atomicAdd(&Sg[tid], sS[tid]); atomicAdd(&Qg[tid], sQ[tid]); }
}

// ---------------- BN folding kernels (self-zeroing) --------------------------
__global__ void stats1_kernel(const float* __restrict__ g, const float* __restrict__ bt) {
    int t = threadIdx.x;
    const float invN = 1.0f / (float)N_NODES;
    float m = g_S1[t] * invN;
    float v = fmaxf(g_Q1[t] * invN - m * m, 0.f);
    g_S1[t] = 0.f; g_Q1[t] = 0.f;
    float r = rsqrtf(v + BN_EPS);
    float sc = r * g[t];
    g_SC1[t] = sc;
    g_SH1[t] = bt[t] - m * sc;
}

__global__ void stats2_kernel(const float* __restrict__ g2,
                              const float* __restrict__ go,
                              const float* __restrict__ bo) {
    int t = threadIdx.x;
    const float invN = 1.0f / (float)N_NODES;
    float m = g_S2[t] * invN;
    float v = fmaxf(g_Q2[t] * invN - m * m, 0.f);
    g_S2[t] = 0.f; g_Q2[t] = 0.f;
    float r2 = rsqrtf(v + BN_EPS);
    float gg = g2[t];
    float vy = gg * gg * v * r2 * r2;            // exact var of BN2 output
    float sc3 = rsqrtf(vy + BN_EPS) * go[t];
    float total = r2 * gg * sc3;
    g_SC2[t] = total;
    g_SH2[t] = bo[t] - m * total;
}

// H = relu(AGG * sc2 + sh2); if WRITE_AGG also primes g_AGG = H for next layer
template <bool WRITE_AGG>
__global__ void apply_relu_kernel(float* __restrict__ H) {
    int i = blockIdx.x * blockDim.x + threadIdx.x;
    if (i >= N_NODES * (DIM / 4)) return;
    int k = (i & 31) * 4;
    float4 v = reinterpret_cast<float4*>(g_AGG)[i];
    v.x = fmaxf(fmaf(v.x, g_SC2[k + 0], g_SH2[k + 0]), 0.f);
    v.y = fmaxf(fmaf(v.y, g_SC2[k + 1], g_SH2[k + 1]), 0.f);
    v.z = fmaxf(fmaf(v.z, g_SC2[k + 2], g_SH2[k + 2]), 0.f);
    v.w = fmaxf(fmaf(v.w, g_SC2[k + 3], g_SH2[k + 3]), 0.f);
    reinterpret_cast<float4*>(H)[i] = v;
    if (WRITE_AGG) reinterpret_cast<float4*>(g_AGG)[i] = v;
}

// ---------------- pooling + classifier ---------------------------------------
__global__ void seg_bounds_kernel(const int* __restrict__ batch) {
    int n = blockIdx.x * blockDim.x + threadIdx.x;
    if (n > N_NODES) return;
    int prev = (n == 0) ? -1 : batch[n - 1];
    int cur = (n == N_NODES) ? N_GRAPHS : batch[n];
    for (int g = prev + 1; g <= cur; g++) g_gstart[g] = n;
}

__global__ void graph_fc_kernel(const float* __restrict__ H,
                                const float* __restrict__ fcW,
                                const float* __restrict__ fcb,
                                float* __restrict__ Gout,
                                float* __restrict__ Cout) {
    int g = blockIdx.x;
    int t = threadIdx.x;
    int beg = g_gstart[g], end = g_gstart[g + 1];
    float s = 0.f;
    for (int r = beg; r < end; r++) s += H[r * DIM + t];
    float cnt = fmaxf((float)(end - beg), 1.0f);
    float ge = s / cnt;
    Gout[g * DIM + t] = ge;
    __shared__ float r0[DIM], r1[DIM];
    r0[t] = ge * fcW[t * 2 + 0];
    r1[t] = ge * fcW[t * 2 + 1];
    __syncthreads();
    for (int sh = 64; sh > 0; sh >>= 1) {
        if (t < sh) { r0[t] += r0[t + sh]; r1[t] += r1[t + sh]; }
        __syncthreads();
    }
    if (t == 0) {
        Cout[g * 2 + 0] = r0[0] + fcb[0];
        Cout[g * 2 + 1] = r1[0] + fcb[1];
    }
}

// ---------------- launcher ---------------------------------------------------
extern "C" void kernel_launch(void* const* d_in, const int* in_sizes, int n_in,
                              void* d_out, int out_size) {
    const float* x     = (const float*)d_in[0];
    const int*   ei    = (const int*)d_in[1];
    const int*   batch = (const int*)d_in[2];
    const float* W1    = (const float*)d_in[3];
    const float* b1    = (const float*)d_in[4];
    const float* g1    = (const float*)d_in[5];
    const float* bt1   = (const float*)d_in[6];
    const float* W2    = (const float*)d_in[7];
    const float* b2    = (const float*)d_in[8];
    const float* g2    = (const float*)d_in[9];
    // d_in[10] (bt2) cancels analytically in BN2∘BN3
    const float* go    = (const float*)d_in[11];
    const float* bo    = (const float*)d_in[12];
    const float* fcW   = (const float*)d_in[13];
    const float* fcb   = (const float*)d_in[14];

    float* out  = (float*)d_out;
    float* Hout = out;
    float* Gout = out + (size_t)N_NODES * DIM;
    float* Cout = Gout + (size_t)N_GRAPHS * DIM;

    const int* src = ei;
    const int* dst = ei + N_EDGES;

    static bool attr_set = false;
    if (!attr_set) {
        cudaFuncSetAttribute(gemm_mma_kernel<1>, cudaFuncAttributeMaxDynamicSharedMemorySize, SMB_TOTAL);
        cudaFuncSetAttribute(gemm_mma_kernel<2>, cudaFuncAttributeMaxDynamicSharedMemorySize, SMB_TOTAL);
        attr_set = true;
    }

    const int nCopyBlocks    = (N_NODES * (DIM / 4)) / 256;      // 12500
    const int nScatterBlocks = (SCATTER_HALF + 255) / 256;       // 37500
    const int nGemmBlocks    = (N_NODES + 127) / 128;            // 782

    wprep_kernel<<<(6 * 4096 + 255) / 256, 256>>>(W1, W2);
    seg_bounds_kernel<<<(N_NODES + 256) / 256, 256>>>(batch);

    for (int i = 0; i < N_LAYERS; i++) {
        const float* Hin = (i == 0) ? x : Hout;
        if (i == 0) copy_to_agg_kernel<<<nCopyBlocks, 256>>>(Hin);
        scatter_add_kernel<<<nScatterBlocks, 256>>>(Hin, src, dst);
        gemm_mma_kernel<1><<<nGemmBlocks, 256, SMB_TOTAL>>>(i, b1 + i * DIM);
        stats1_kernel<<<1, 128>>>(g1 + i * DIM, bt1 + i * DIM);
        gemm_mma_kernel<2><<<nGemmBlocks, 256, SMB_TOTAL>>>(i + 3, b2 + i * DIM);
        stats2_kernel<<<1, 128>>>(g2 + i * DIM, go + i * DIM, bo + i * DIM);
        if (i + 1 < N_LAYERS)
            apply_relu_kernel<true><<<nCopyBlocks, 256>>>(Hout);
        else
            apply_relu_kernel<false><<<nCopyBlocks, 256>>>(Hout);
    }

    graph_fc_kernel<<<N_GRAPHS, 128>>>(Hout, fcW, fcb, Gout, Cout);
}

// round 7
// speedup vs baseline: 1.9970x; 1.0044x over previous
#include <cuda_runtime.h>
#include <cuda_bf16.h>
#include <cstdint>

#define N_NODES 100000
#define N_EDGES 600000
#define N_GRAPHS 512
#define DIM 128
#define N_LAYERS 3
#define BN_EPS 1e-5f

// ---------------- scratch (device globals; no allocation allowed) ----------
__device__ __align__(16) float g_AGG[(size_t)N_NODES * DIM];
__device__ __align__(16) float g_T[(size_t)N_NODES * DIM];
__device__ float g_S1[DIM], g_Q1[DIM], g_S2[DIM], g_Q2[DIM];
__device__ float g_SC1[DIM], g_SH1[DIM], g_SC2[DIM], g_SH2[DIM];
__device__ int g_gstart[N_GRAPHS + 1];
// W fragments, interleaved {hi0,hi1,lo0,lo1}: [mat][kb 8][nb 16][lane 32][4]
__device__ __align__(16) uint32_t g_Wfrag[6 * 16384];

// ---------------- helpers ----------------------------------------------------
__device__ __forceinline__ uint32_t pack_bf16x2(float f0, float f1) {
    __nv_bfloat162 h = __floats2bfloat162_rn(f0, f1);
    return *reinterpret_cast<uint32_t*>(&h);
}
__device__ __forceinline__ void split2(float2 v, uint32_t& hi, uint32_t& lo) {
    __nv_bfloat16 h0 = __float2bfloat16_rn(v.x);
    __nv_bfloat16 h1 = __float2bfloat16_rn(v.y);
    float l0 = v.x - __bfloat162float(h0);
    float l1 = v.y - __bfloat162float(h1);
    __nv_bfloat162 hp; hp.x = h0; hp.y = h1;
    hi = *reinterpret_cast<uint32_t*>(&hp);
    lo = pack_bf16x2(l0, l1);
}
__device__ __forceinline__ void mma_bf16(float c[4], const uint32_t a[4], uint32_t b0, uint32_t b1) {
    asm volatile(
        "mma.sync.aligned.m16n8k16.row.col.f32.bf16.bf16.f32 "
        "{%0,%1,%2,%3}, {%4,%5,%6,%7}, {%8,%9}, {%0,%1,%2,%3};"
        : "+f"(c[0]), "+f"(c[1]), "+f"(c[2]), "+f"(c[3])
        : "r"(a[0]), "r"(a[1]), "r"(a[2]), "r"(a[3]), "r"(b0), "r"(b1));
}

// ---------------- W prep: split + interleaved fragment layout ----------------
// frag element: k = kb*16 + (lane%4)*2 + r*8 + {0,1}, n = nb*8 + lane/4
__global__ void wprep_kernel(const float* __restrict__ W1, const float* __restrict__ W2) {
    int idx = blockIdx.x * blockDim.x + threadIdx.x;   // 0 .. 6*4096-1 (frag quads)
    if (idx >= 6 * 4096) return;
    int mat = idx >> 12;
    int e = idx & 4095;
    int lane = e & 31;
    int nb = (e >> 5) & 15;
    int kb = e >> 9;
    int n = nb * 8 + (lane >> 2);
    const float* W = (mat < 3) ? (W1 + (size_t)mat * 16384)
                               : (W2 + (size_t)(mat - 3) * 16384);
    uint32_t hi0, lo0, hi1, lo1;
    {
        int k0 = kb * 16 + (lane & 3) * 2;
        split2(make_float2(W[k0 * 128 + n], W[(k0 + 1) * 128 + n]), hi0, lo0);
        int k1 = k0 + 8;
        split2(make_float2(W[k1 * 128 + n], W[(k1 + 1) * 128 + n]), hi1, lo1);
    }
    uint4 q = make_uint4(hi0, hi1, lo0, lo1);
    reinterpret_cast<uint4*>(g_Wfrag)[mat * 4096 + e] = q;
}

// ---------------- aggregation -------------------------------------------------
__global__ void copy_to_agg_kernel(const float* __restrict__ H) {
    int i = blockIdx.x * blockDim.x + threadIdx.x;
    if (i < N_NODES * (DIM / 4))
        reinterpret_cast<float4*>(g_AGG)[i] = reinterpret_cast<const float4*>(H)[i];
}

// AGG[dst] += H[src] — 4 independent edge-chunks per thread for MLP
#define SCATTER_WORK (N_EDGES * 32)          // float4 chunks total
#define SCATTER_QTR (SCATTER_WORK / 4)
__global__ void scatter_add_kernel(const float* __restrict__ H,
                                   const int* __restrict__ src,
                                   const int* __restrict__ dst) {
    int idx = blockIdx.x * blockDim.x + threadIdx.x;
    if (idx >= SCATTER_QTR) return;
    const int j = idx & 31;
    int e0 = idx >> 5;
    int e1 = (idx + SCATTER_QTR) >> 5;
    int e2 = (idx + 2 * SCATTER_QTR) >> 5;
    int e3 = (idx + 3 * SCATTER_QTR) >> 5;
    int s0 = __ldg(&src[e0]), d0 = __ldg(&dst[e0]);
    int s1 = __ldg(&src[e1]), d1 = __ldg(&dst[e1]);
    int s2 = __ldg(&src[e2]), d2 = __ldg(&dst[e2]);
    int s3 = __ldg(&src[e3]), d3 = __ldg(&dst[e3]);
    float4 v0 = reinterpret_cast<const float4*>(H)[s0 * 32 + j];
    float4 v1 = reinterpret_cast<const float4*>(H)[s1 * 32 + j];
    float4 v2 = reinterpret_cast<const float4*>(H)[s2 * 32 + j];
    float4 v3 = reinterpret_cast<const float4*>(H)[s3 * 32 + j];
    atomicAdd(reinterpret_cast<float4*>(g_AGG) + d0 * 32 + j, v0);
    atomicAdd(reinterpret_cast<float4*>(g_AGG) + d1 * 32 + j, v1);
    atomicAdd(reinterpret_cast<float4*>(g_AGG) + d2 * 32 + j, v2);
    atomicAdd(reinterpret_cast<float4*>(g_AGG) + d3 * 32 + j, v3);
}

// ---------------- HMMA GEMM + column stats -----------------------------------
// PHASE 1: T   = AGG @ W + b    (stats -> S1/Q1)
// PHASE 2: AGG = BN1(T) @ W + b (affine on A-load; stats -> S2/Q2)
// Block: 128 rows x 128 cols, 8 warps; warp w -> rows [16w,16w+16).
#define SMB_BFRAG 0
#define SMB_BIAS 65536
#define SMB_SCL 66048
#define SMB_SHF 66560
#define SMB_SS 67072
#define SMB_SQ 67584
#define SMB_TOTAL 68096

template <int PHASE>
__global__ void __launch_bounds__(256) gemm_mma_kernel(int mat, const float* __restrict__ bias) {
    const float* A   = (PHASE == 1) ? g_AGG : g_T;
    float*       Out = (PHASE == 1) ? g_T : g_AGG;
    float*       Sg  = (PHASE == 1) ? g_S1 : g_S2;
    float*       Qg  = (PHASE == 1) ? g_Q1 : g_Q2;

    extern __shared__ __align__(16) char smem[];
    uint32_t* sBf  = reinterpret_cast<uint32_t*>(smem + SMB_BFRAG);
    float* sBias = reinterpret_cast<float*>(smem + SMB_BIAS);
    float* sScl  = reinterpret_cast<float*>(smem + SMB_SCL);
    float* sShf  = reinterpret_cast<float*>(smem + SMB_SHF);
    float* sS    = reinterpret_cast<float*>(smem + SMB_SS);
    float* sQ    = reinterpret_cast<float*>(smem + SMB_SQ);

    const int tid = threadIdx.x;
    const int wid = tid >> 5;
    const int lane = tid & 31;
    const int qrow = lane >> 2;
    const int qk = (lane & 3) * 2;
    const int row0 = blockIdx.x * 128;

    {
        const uint4* wf = reinterpret_cast<const uint4*>(g_Wfrag + mat * 16384);
        uint4* bf = reinterpret_cast<uint4*>(sBf);
#pragma unroll
        for (int i = 0; i < 16; i++) {
            int idx = tid + i * 256;
            bf[idx] = wf[idx];
        }
    }
    if (tid < DIM) {
        sBias[tid] = bias[tid];
        sS[tid] = 0.f; sQ[tid] = 0.f;
        if (PHASE == 2) { sScl[tid] = g_SC1[tid]; sShf[tid] = g_SH1[tid]; }
    }
    __syncthreads();

    const int r0 = row0 + wid * 16 + qrow;
    const int r1 = r0 + 8;
    const bool v0 = (r0 < N_NODES);
    const bool v1 = (r1 < N_NODES);
    const float* a0p = A + (size_t)r0 * DIM;
    const float* a1p = A + (size_t)r1 * DIM;

    float c[16][4];
#pragma unroll
    for (int nb = 0; nb < 16; nb++) {
        c[nb][0] = 0.f; c[nb][1] = 0.f; c[nb][2] = 0.f; c[nb][3] = 0.f;
    }

#pragma unroll
    for (int kb = 0; kb < 8; kb++) {
        const int c0 = kb * 16 + qk;
        float2 x00 = make_float2(0.f, 0.f), x01 = x00, x10 = x00, x11 = x00;
        if (v0) {
            x00 = *reinterpret_cast<const float2*>(a0p + c0);
            x01 = *reinterpret_cast<const float2*>(a0p + c0 + 8);
        }
        if (v1) {
            x10 = *reinterpret_cast<const float2*>(a1p + c0);
            x11 = *reinterpret_cast<const float2*>(a1p + c0 + 8);
        }
        if (PHASE == 2) {
            x00.x = fmaf(x00.x, sScl[c0], sShf[c0]);
            x00.y = fmaf(x00.y, sScl[c0 + 1], sShf[c0 + 1]);
            x01.x = fmaf(x01.x, sScl[c0 + 8], sShf[c0 + 8]);
            x01.y = fmaf(x01.y, sScl[c0 + 9], sShf[c0 + 9]);
            x10.x = fmaf(x10.x, sScl[c0], sShf[c0]);
            x10.y = fmaf(x10.y, sScl[c0 + 1], sShf[c0 + 1]);
            x11.x = fmaf(x11.x, sScl[c0 + 8], sShf[c0 + 8]);
            x11.y = fmaf(x11.y, sScl[c0 + 9], sShf[c0 + 9]);
        }
        uint32_t ahi[4], alo[4];
        split2(x00, ahi[0], alo[0]);
        split2(x10, ahi[1], alo[1]);
        split2(x01, ahi[2], alo[2]);
        split2(x11, ahi[3], alo[3]);

#pragma unroll
        for (int nb = 0; nb < 16; nb++) {
            const uint4 b = *reinterpret_cast<const uint4*>(&sBf[((kb * 16 + nb) * 32 + lane) * 4]);
            mma_bf16(c[nb], ahi, b.x, b.y);
            mma_bf16(c[nb], ahi, b.z, b.w);
            mma_bf16(c[nb], alo, b.x, b.y);
        }
    }

    // ---- epilogue: bias + store + column stats ----
#pragma unroll
    for (int nb = 0; nb < 16; nb++) {
        const int cn = nb * 8 + qk;
        const float b0 = sBias[cn], b1 = sBias[cn + 1];
        float o00 = v0 ? (c[nb][0] + b0) : 0.f;
        float o01 = v0 ? (c[nb][1] + b1) : 0.f;
        float o10 = v1 ? (c[nb][2] + b0) : 0.f;
        float o11 = v1 ? (c[nb][3] + b1) : 0.f;
        if (v0) *reinterpret_cast<float2*>(Out + (size_t)r0 * DIM + cn) = make_float2(o00, o01);
        if (v1) *reinterpret_cast<float2*>(Out + (size_t)r1 * DIM + cn) = make_float2(o10, o11);
        float s0 = o00 + o10, s1 = o01 + o11;
        float q0 = o00 * o00 + o10 * o10, q1 = o01 * o01 + o11 * o11;
#pragma unroll
        for (int off = 4; off < 32; off <<= 1) {
            s0 += __shfl_down_sync(0xFFFFFFFF, s0, off);
            s1 += __shfl_down_sync(0xFFFFFFFF, s1, off);
            q0 += __shfl_down_sync(0xFFFFFFFF, q0, off);
            q1 += __shfl_down_sync(0xFFFFFFFF, q1, off);
        }
        if (lane < 4) {
            atomicAdd(&sS[cn], s0);
            atomicAdd(&sS[cn + 1], s1);
            atomicAdd(&sQ[cn], q0);
            atomicAdd(&sQ[cn + 1], q1);
        }
    }
    __syncthreads();
    if (tid < DIM) { atomicAdd(&Sg[tid], sS[tid]); atomicAdd(&Qg[tid], sQ[tid]); }
}

// ---------------- BN folding kernels (self-zeroing) --------------------------
__global__ void stats1_kernel(const float* __restrict__ g, const float* __restrict__ bt) {
    int t = threadIdx.x;
    const float invN = 1.0f / (float)N_NODES;
    float m = g_S1[t] * invN;
    float v = fmaxf(g_Q1[t] * invN - m * m, 0.f);
    g_S1[t] = 0.f; g_Q1[t] = 0.f;
    float r = rsqrtf(v + BN_EPS);
    float sc = r * g[t];
    g_SC1[t] = sc;
    g_SH1[t] = bt[t] - m * sc;
}

__global__ void stats2_kernel(const float* __restrict__ g2,
                              const float* __restrict__ go,
                              const float* __restrict__ bo) {
    int t = threadIdx.x;
    const float invN = 1.0f / (float)N_NODES;
    float m = g_S2[t] * invN;
    float v = fmaxf(g_Q2[t] * invN - m * m, 0.f);
    g_S2[t] = 0.f; g_Q2[t] = 0.f;
    float r2 = rsqrtf(v + BN_EPS);
    float gg = g2[t];
    float vy = gg * gg * v * r2 * r2;            // exact var of BN2 output
    float sc3 = rsqrtf(vy + BN_EPS) * go[t];
    float total = r2 * gg * sc3;
    g_SC2[t] = total;
    g_SH2[t] = bo[t] - m * total;
}

// H = relu(AGG * sc2 + sh2); if WRITE_AGG also primes g_AGG = H for next layer
template <bool WRITE_AGG>
__global__ void apply_relu_kernel(float* __restrict__ H) {
    int i = blockIdx.x * blockDim.x + threadIdx.x;
    if (i >= N_NODES * (DIM / 4)) return;
    int k = (i & 31) * 4;
    float4 v = reinterpret_cast<float4*>(g_AGG)[i];
    v.x = fmaxf(fmaf(v.x, g_SC2[k + 0], g_SH2[k + 0]), 0.f);
    v.y = fmaxf(fmaf(v.y, g_SC2[k + 1], g_SH2[k + 1]), 0.f);
    v.z = fmaxf(fmaf(v.z, g_SC2[k + 2], g_SH2[k + 2]), 0.f);
    v.w = fmaxf(fmaf(v.w, g_SC2[k + 3], g_SH2[k + 3]), 0.f);
    reinterpret_cast<float4*>(H)[i] = v;
    if (WRITE_AGG) reinterpret_cast<float4*>(g_AGG)[i] = v;
}

// ---------------- pooling + classifier ---------------------------------------
__global__ void seg_bounds_kernel(const int* __restrict__ batch) {
    int n = blockIdx.x * blockDim.x + threadIdx.x;
    if (n > N_NODES) return;
    int prev = (n == 0) ? -1 : batch[n - 1];
    int cur = (n == N_NODES) ? N_GRAPHS : batch[n];
    for (int g = prev + 1; g <= cur; g++) g_gstart[g] = n;
}

__global__ void graph_fc_kernel(const float* __restrict__ H,
                                const float* __restrict__ fcW,
                                const float* __restrict__ fcb,
                                float* __restrict__ Gout,
                                float* __restrict__ Cout) {
    int g = blockIdx.x;
    int t = threadIdx.x;
    int beg = g_gstart[g], end = g_gstart[g + 1];
    float s = 0.f;
    for (int r = beg; r < end; r++) s += H[r * DIM + t];
    float cnt = fmaxf((float)(end - beg), 1.0f);
    float ge = s / cnt;
    Gout[g * DIM + t] = ge;
    __shared__ float r0[DIM], r1[DIM];
    r0[t] = ge * fcW[t * 2 + 0];
    r1[t] = ge * fcW[t * 2 + 1];
    __syncthreads();
    for (int sh = 64; sh > 0; sh >>= 1) {
        if (t < sh) { r0[t] += r0[t + sh]; r1[t] += r1[t + sh]; }
        __syncthreads();
    }
    if (t == 0) {
        Cout[g * 2 + 0] = r0[0] + fcb[0];
        Cout[g * 2 + 1] = r1[0] + fcb[1];
    }
}

// ---------------- launcher ---------------------------------------------------
extern "C" void kernel_launch(void* const* d_in, const int* in_sizes, int n_in,
                              void* d_out, int out_size) {
    const float* x     = (const float*)d_in[0];
    const int*   ei    = (const int*)d_in[1];
    const int*   batch = (const int*)d_in[2];
    const float* W1    = (const float*)d_in[3];
    const float* b1    = (const float*)d_in[4];
    const float* g1    = (const float*)d_in[5];
    const float* bt1   = (const float*)d_in[6];
    const float* W2    = (const float*)d_in[7];
    const float* b2    = (const float*)d_in[8];
    const float* g2    = (const float*)d_in[9];
    // d_in[10] (bt2) cancels analytically in BN2∘BN3
    const float* go    = (const float*)d_in[11];
    const float* bo    = (const float*)d_in[12];
    const float* fcW   = (const float*)d_in[13];
    const float* fcb   = (const float*)d_in[14];

    float* out  = (float*)d_out;
    float* Hout = out;
    float* Gout = out + (size_t)N_NODES * DIM;
    float* Cout = Gout + (size_t)N_GRAPHS * DIM;

    const int* src = ei;
    const int* dst = ei + N_EDGES;

    static bool attr_set = false;
    if (!attr_set) {
        cudaFuncSetAttribute(gemm_mma_kernel<1>, cudaFuncAttributeMaxDynamicSharedMemorySize, SMB_TOTAL);
        cudaFuncSetAttribute(gemm_mma_kernel<2>, cudaFuncAttributeMaxDynamicSharedMemorySize, SMB_TOTAL);
        attr_set = true;
    }

    const int nCopyBlocks    = (N_NODES * (DIM / 4)) / 256;      // 12500
    const int nScatterBlocks = (SCATTER_QTR + 255) / 256;        // 18750
    const int nGemmBlocks    = (N_NODES + 127) / 128;            // 782

    wprep_kernel<<<(6 * 4096 + 255) / 256, 256>>>(W1, W2);
    seg_bounds_kernel<<<(N_NODES + 256) / 256, 256>>>(batch);

    for (int i = 0; i < N_LAYERS; i++) {
        const float* Hin = (i == 0) ? x : Hout;
        if (i == 0) copy_to_agg_kernel<<<nCopyBlocks, 256>>>(Hin);
        scatter_add_kernel<<<nScatterBlocks, 256>>>(Hin, src, dst);
        gemm_mma_kernel<1><<<nGemmBlocks, 256, SMB_TOTAL>>>(i, b1 + i * DIM);
        stats1_kernel<<<1, 128>>>(g1 + i * DIM, bt1 + i * DIM);
        gemm_mma_kernel<2><<<nGemmBlocks, 256, SMB_TOTAL>>>(i + 3, b2 + i * DIM);
        stats2_kernel<<<1, 128>>>(g2 + i * DIM, go + i * DIM, bo + i * DIM);
        if (i + 1 < N_LAYERS)
            apply_relu_kernel<true><<<nCopyBlocks, 256>>>(Hout);
        else
            apply_relu_kernel<false><<<nCopyBlocks, 256>>>(Hout);
    }

    graph_fc_kernel<<<N_GRAPHS, 128>>>(Hout, fcW, fcb, Gout, Cout);
}

// round 8
// speedup vs baseline: 2.0617x; 1.0324x over previous
#include <cuda_runtime.h>
#include <cuda_bf16.h>
#include <cstdint>

#define N_NODES 100000
#define N_EDGES 600000
#define N_GRAPHS 512
#define DIM 128
#define N_LAYERS 3
#define BN_EPS 1e-5f

// ---------------- scratch (device globals; no allocation allowed) ----------
__device__ __align__(16) float g_AGG[(size_t)N_NODES * DIM];
__device__ __align__(16) float g_T[(size_t)N_NODES * DIM];
__device__ float g_S1[DIM], g_Q1[DIM], g_S2[DIM], g_Q2[DIM];
__device__ int g_gstart[N_GRAPHS + 1];
// W fragments, interleaved {hi0,hi1,lo0,lo1}: [mat][kb 8][nb 16][lane 32][4]
__device__ __align__(16) uint32_t g_Wfrag[6 * 16384];

// ---------------- helpers ----------------------------------------------------
__device__ __forceinline__ uint32_t pack_bf16x2(float f0, float f1) {
    __nv_bfloat162 h = __floats2bfloat162_rn(f0, f1);
    return *reinterpret_cast<uint32_t*>(&h);
}
__device__ __forceinline__ void split2(float2 v, uint32_t& hi, uint32_t& lo) {
    __nv_bfloat16 h0 = __float2bfloat16_rn(v.x);
    __nv_bfloat16 h1 = __float2bfloat16_rn(v.y);
    float l0 = v.x - __bfloat162float(h0);
    float l1 = v.y - __bfloat162float(h1);
    __nv_bfloat162 hp; hp.x = h0; hp.y = h1;
    hi = *reinterpret_cast<uint32_t*>(&hp);
    lo = pack_bf16x2(l0, l1);
}
__device__ __forceinline__ void mma_bf16(float c[4], const uint32_t a[4], uint32_t b0, uint32_t b1) {
    asm volatile(
        "mma.sync.aligned.m16n8k16.row.col.f32.bf16.bf16.f32 "
        "{%0,%1,%2,%3}, {%4,%5,%6,%7}, {%8,%9}, {%0,%1,%2,%3};"
        : "+f"(c[0]), "+f"(c[1]), "+f"(c[2]), "+f"(c[3])
        : "r"(a[0]), "r"(a[1]), "r"(a[2]), "r"(a[3]), "r"(b0), "r"(b1));
}

// ---------------- W prep: split + interleaved fragment layout ----------------
// frag element: k = kb*16 + (lane%4)*2 + r*8 + {0,1}, n = nb*8 + lane/4
__global__ void wprep_kernel(const float* __restrict__ W1, const float* __restrict__ W2) {
    int idx = blockIdx.x * blockDim.x + threadIdx.x;   // 0 .. 6*4096-1 (frag quads)
    if (idx >= 6 * 4096) return;
    int mat = idx >> 12;
    int e = idx & 4095;
    int lane = e & 31;
    int nb = (e >> 5) & 15;
    int kb = e >> 9;
    int n = nb * 8 + (lane >> 2);
    const float* W = (mat < 3) ? (W1 + (size_t)mat * 16384)
                               : (W2 + (size_t)(mat - 3) * 16384);
    uint32_t hi0, lo0, hi1, lo1;
    {
        int k0 = kb * 16 + (lane & 3) * 2;
        split2(make_float2(W[k0 * 128 + n], W[(k0 + 1) * 128 + n]), hi0, lo0);
        int k1 = k0 + 8;
        split2(make_float2(W[k1 * 128 + n], W[(k1 + 1) * 128 + n]), hi1, lo1);
    }
    uint4 q = make_uint4(hi0, hi1, lo0, lo1);
    reinterpret_cast<uint4*>(g_Wfrag)[mat * 4096 + e] = q;
}

// ---------------- aggregation -------------------------------------------------
__global__ void copy_to_agg_kernel(const float* __restrict__ H) {
    int i = blockIdx.x * blockDim.x + threadIdx.x;
    if (i < N_NODES * (DIM / 4))
        reinterpret_cast<float4*>(g_AGG)[i] = reinterpret_cast<const float4*>(H)[i];
}

// AGG[dst] += H[src] — 4 independent edge-chunks per thread for MLP.
// Block 0 also zeroes the BN accumulators for this layer (runs before gemm<1>).
#define SCATTER_WORK (N_EDGES * 32)          // float4 chunks total
#define SCATTER_QTR (SCATTER_WORK / 4)
__global__ void scatter_add_kernel(const float* __restrict__ H,
                                   const int* __restrict__ src,
                                   const int* __restrict__ dst) {
    int idx = blockIdx.x * blockDim.x + threadIdx.x;
    if (blockIdx.x == 0 && threadIdx.x < DIM) {
        g_S1[threadIdx.x] = 0.f; g_Q1[threadIdx.x] = 0.f;
        g_S2[threadIdx.x] = 0.f; g_Q2[threadIdx.x] = 0.f;
    }
    if (idx >= SCATTER_QTR) return;
    const int j = idx & 31;
    int e0 = idx >> 5;
    int e1 = (idx + SCATTER_QTR) >> 5;
    int e2 = (idx + 2 * SCATTER_QTR) >> 5;
    int e3 = (idx + 3 * SCATTER_QTR) >> 5;
    int s0 = __ldg(&src[e0]), d0 = __ldg(&dst[e0]);
    int s1 = __ldg(&src[e1]), d1 = __ldg(&dst[e1]);
    int s2 = __ldg(&src[e2]), d2 = __ldg(&dst[e2]);
    int s3 = __ldg(&src[e3]), d3 = __ldg(&dst[e3]);
    float4 v0 = reinterpret_cast<const float4*>(H)[s0 * 32 + j];
    float4 v1 = reinterpret_cast<const float4*>(H)[s1 * 32 + j];
    float4 v2 = reinterpret_cast<const float4*>(H)[s2 * 32 + j];
    float4 v3 = reinterpret_cast<const float4*>(H)[s3 * 32 + j];
    atomicAdd(reinterpret_cast<float4*>(g_AGG) + d0 * 32 + j, v0);
    atomicAdd(reinterpret_cast<float4*>(g_AGG) + d1 * 32 + j, v1);
    atomicAdd(reinterpret_cast<float4*>(g_AGG) + d2 * 32 + j, v2);
    atomicAdd(reinterpret_cast<float4*>(g_AGG) + d3 * 32 + j, v3);
}

// ---------------- HMMA GEMM + column stats -----------------------------------
// PHASE 1: T   = AGG @ W + b    (stats -> S1/Q1)
// PHASE 2: AGG = BN1(T) @ W + b (BN1 coefficients computed in-block from
//                                S1/Q1; stats -> S2/Q2)
// Block: 128 rows x 128 cols, 8 warps; warp w -> rows [16w,16w+16).
#define SMB_BFRAG 0
#define SMB_BIAS 65536
#define SMB_SCL 66048
#define SMB_SHF 66560
#define SMB_SS 67072
#define SMB_SQ 67584
#define SMB_TOTAL 68096

template <int PHASE>
__global__ void __launch_bounds__(256) gemm_mma_kernel(int mat,
                                                       const float* __restrict__ bias,
                                                       const float* __restrict__ bn_g,
                                                       const float* __restrict__ bn_b) {
    const float* A   = (PHASE == 1) ? g_AGG : g_T;
    float*       Out = (PHASE == 1) ? g_T : g_AGG;
    float*       Sg  = (PHASE == 1) ? g_S1 : g_S2;
    float*       Qg  = (PHASE == 1) ? g_Q1 : g_Q2;

    extern __shared__ __align__(16) char smem[];
    uint32_t* sBf  = reinterpret_cast<uint32_t*>(smem + SMB_BFRAG);
    float* sBias = reinterpret_cast<float*>(smem + SMB_BIAS);
    float* sScl  = reinterpret_cast<float*>(smem + SMB_SCL);
    float* sShf  = reinterpret_cast<float*>(smem + SMB_SHF);
    float* sS    = reinterpret_cast<float*>(smem + SMB_SS);
    float* sQ    = reinterpret_cast<float*>(smem + SMB_SQ);

    const int tid = threadIdx.x;
    const int wid = tid >> 5;
    const int lane = tid & 31;
    const int qrow = lane >> 2;
    const int qk = (lane & 3) * 2;
    const int row0 = blockIdx.x * 128;

    {
        const uint4* wf = reinterpret_cast<const uint4*>(g_Wfrag + mat * 16384);
        uint4* bf = reinterpret_cast<uint4*>(sBf);
#pragma unroll
        for (int i = 0; i < 16; i++) {
            int idx = tid + i * 256;
            bf[idx] = wf[idx];
        }
    }
    if (tid < DIM) {
        sBias[tid] = bias[tid];
        sS[tid] = 0.f; sQ[tid] = 0.f;
        if (PHASE == 2) {
            // BN1 fold: S1/Q1 are final after gemm<1> kernel boundary
            const float invN = 1.0f / (float)N_NODES;
            float m = g_S1[tid] * invN;
            float v = fmaxf(g_Q1[tid] * invN - m * m, 0.f);
            float sc = rsqrtf(v + BN_EPS) * bn_g[tid];
            sScl[tid] = sc;
            sShf[tid] = bn_b[tid] - m * sc;
        }
    }
    __syncthreads();

    const int r0 = row0 + wid * 16 + qrow;
    const int r1 = r0 + 8;
    const bool v0 = (r0 < N_NODES);
    const bool v1 = (r1 < N_NODES);
    const float* a0p = A + (size_t)r0 * DIM;
    const float* a1p = A + (size_t)r1 * DIM;

    float c[16][4];
#pragma unroll
    for (int nb = 0; nb < 16; nb++) {
        c[nb][0] = 0.f; c[nb][1] = 0.f; c[nb][2] = 0.f; c[nb][3] = 0.f;
    }

#pragma unroll
    for (int kb = 0; kb < 8; kb++) {
        const int c0 = kb * 16 + qk;
        float2 x00 = make_float2(0.f, 0.f), x01 = x00, x10 = x00, x11 = x00;
        if (v0) {
            x00 = *reinterpret_cast<const float2*>(a0p + c0);
            x01 = *reinterpret_cast<const float2*>(a0p + c0 + 8);
        }
        if (v1) {
            x10 = *reinterpret_cast<const float2*>(a1p + c0);
            x11 = *reinterpret_cast<const float2*>(a1p + c0 + 8);
        }
        if (PHASE == 2) {
            x00.x = fmaf(x00.x, sScl[c0], sShf[c0]);
            x00.y = fmaf(x00.y, sScl[c0 + 1], sShf[c0 + 1]);
            x01.x = fmaf(x01.x, sScl[c0 + 8], sShf[c0 + 8]);
            x01.y = fmaf(x01.y, sScl[c0 + 9], sShf[c0 + 9]);
            x10.x = fmaf(x10.x, sScl[c0], sShf[c0]);
            x10.y = fmaf(x10.y, sScl[c0 + 1], sShf[c0 + 1]);
            x11.x = fmaf(x11.x, sScl[c0 + 8], sShf[c0 + 8]);
            x11.y = fmaf(x11.y, sScl[c0 + 9], sShf[c0 + 9]);
        }
        uint32_t ahi[4], alo[4];
        split2(x00, ahi[0], alo[0]);
        split2(x10, ahi[1], alo[1]);
        split2(x01, ahi[2], alo[2]);
        split2(x11, ahi[3], alo[3]);

#pragma unroll
        for (int nb = 0; nb < 16; nb++) {
            const uint4 b = *reinterpret_cast<const uint4*>(&sBf[((kb * 16 + nb) * 32 + lane) * 4]);
            mma_bf16(c[nb], ahi, b.x, b.y);
            mma_bf16(c[nb], ahi, b.z, b.w);
            mma_bf16(c[nb], alo, b.x, b.y);
        }
    }

    // ---- epilogue: bias + store + column stats ----
#pragma unroll
    for (int nb = 0; nb < 16; nb++) {
        const int cn = nb * 8 + qk;
        const float b0 = sBias[cn], b1 = sBias[cn + 1];
        float o00 = v0 ? (c[nb][0] + b0) : 0.f;
        float o01 = v0 ? (c[nb][1] + b1) : 0.f;
        float o10 = v1 ? (c[nb][2] + b0) : 0.f;
        float o11 = v1 ? (c[nb][3] + b1) : 0.f;
        if (v0) *reinterpret_cast<float2*>(Out + (size_t)r0 * DIM + cn) = make_float2(o00, o01);
        if (v1) *reinterpret_cast<float2*>(Out + (size_t)r1 * DIM + cn) = make_float2(o10, o11);
        float s0 = o00 + o10, s1 = o01 + o11;
        float q0 = o00 * o00 + o10 * o10, q1 = o01 * o01 + o11 * o11;
#pragma unroll
        for (int off = 4; off < 32; off <<= 1) {
            s0 += __shfl_down_sync(0xFFFFFFFF, s0, off);
            s1 += __shfl_down_sync(0xFFFFFFFF, s1, off);
            q0 += __shfl_down_sync(0xFFFFFFFF, q0, off);
            q1 += __shfl_down_sync(0xFFFFFFFF, q1, off);
        }
        if (lane < 4) {
            atomicAdd(&sS[cn], s0);
            atomicAdd(&sS[cn + 1], s1);
            atomicAdd(&sQ[cn], q0);
            atomicAdd(&sQ[cn + 1], q1);
        }
    }
    __syncthreads();
    if (tid < DIM) { atomicAdd(&Sg[tid], sS[tid]); atomicAdd(&Qg[tid], sQ[tid]); }
}

// H = relu(AGG * sc2 + sh2), BN2∘BN3 coefficients computed in-block from S2/Q2.
// If WRITE_AGG also primes g_AGG = H for next layer.
template <bool WRITE_AGG>
__global__ void apply_relu_kernel(float* __restrict__ H,
                                  const float* __restrict__ g2,
                                  const float* __restrict__ go,
                                  const float* __restrict__ bo) {
    __shared__ float sc2[DIM], sh2[DIM];
    if (threadIdx.x < DIM) {
        int t = threadIdx.x;
        const float invN = 1.0f / (float)N_NODES;
        float m = g_S2[t] * invN;
        float v = fmaxf(g_Q2[t] * invN - m * m, 0.f);
        float r2 = rsqrtf(v + BN_EPS);
        float gg = g2[t];
        float vy = gg * gg * v * r2 * r2;            // exact var of BN2 output
        float sc3 = rsqrtf(vy + BN_EPS) * go[t];
        float total = r2 * gg * sc3;
        sc2[t] = total;
        sh2[t] = bo[t] - m * total;
    }
    __syncthreads();
    int i = blockIdx.x * blockDim.x + threadIdx.x;
    if (i >= N_NODES * (DIM / 4)) return;
    int k = (i & 31) * 4;
    float4 v = reinterpret_cast<float4*>(g_AGG)[i];
    v.x = fmaxf(fmaf(v.x, sc2[k + 0], sh2[k + 0]), 0.f);
    v.y = fmaxf(fmaf(v.y, sc2[k + 1], sh2[k + 1]), 0.f);
    v.z = fmaxf(fmaf(v.z, sc2[k + 2], sh2[k + 2]), 0.f);
    v.w = fmaxf(fmaf(v.w, sc2[k + 3], sh2[k + 3]), 0.f);
    reinterpret_cast<float4*>(H)[i] = v;
    if (WRITE_AGG) reinterpret_cast<float4*>(g_AGG)[i] = v;
}

// ---------------- pooling + classifier ---------------------------------------
__global__ void seg_bounds_kernel(const int* __restrict__ batch) {
    int n = blockIdx.x * blockDim.x + threadIdx.x;
    if (n > N_NODES) return;
    int prev = (n == 0) ? -1 : batch[n - 1];
    int cur = (n == N_NODES) ? N_GRAPHS : batch[n];
    for (int g = prev + 1; g <= cur; g++) g_gstart[g] = n;
}

__global__ void graph_fc_kernel(const float* __restrict__ H,
                                const float* __restrict__ fcW,
                                const float* __restrict__ fcb,
                                float* __restrict__ Gout,
                                float* __restrict__ Cout) {
    int g = blockIdx.x;
    int t = threadIdx.x;
    int beg = g_gstart[g], end = g_gstart[g + 1];
    float s = 0.f;
    for (int r = beg; r < end; r++) s += H[r * DIM + t];
    float cnt = fmaxf((float)(end - beg), 1.0f);
    float ge = s / cnt;
    Gout[g * DIM + t] = ge;
    __shared__ float r0[DIM], r1[DIM];
    r0[t] = ge * fcW[t * 2 + 0];
    r1[t] = ge * fcW[t * 2 + 1];
    __syncthreads();
    for (int sh = 64; sh > 0; sh >>= 1) {
        if (t < sh) { r0[t] += r0[t + sh]; r1[t] += r1[t + sh]; }
        __syncthreads();
    }
    if (t == 0) {
        Cout[g * 2 + 0] = r0[0] + fcb[0];
        Cout[g * 2 + 1] = r1[0] + fcb[1];
    }
}

// ---------------- launcher ---------------------------------------------------
extern "C" void kernel_launch(void* const* d_in, const int* in_sizes, int n_in,
                              void* d_out, int out_size) {
    const float* x     = (const float*)d_in[0];
    const int*   ei    = (const int*)d_in[1];
    const int*   batch = (const int*)d_in[2];
    const float* W1    = (const float*)d_in[3];
    const float* b1    = (const float*)d_in[4];
    const float* g1    = (const float*)d_in[5];
    const float* bt1   = (const float*)d_in[6];
    const float* W2    = (const float*)d_in[7];
    const float* b2    = (const float*)d_in[8];
    const float* g2    = (const float*)d_in[9];
    // d_in[10] (bt2) cancels analytically in BN2∘BN3
    const float* go    = (const float*)d_in[11];
    const float* bo    = (const float*)d_in[12];
    const float* fcW   = (const float*)d_in[13];
    const float* fcb   = (const float*)d_in[14];

    float* out  = (float*)d_out;
    float* Hout = out;
    float* Gout = out + (size_t)N_NODES * DIM;
    float* Cout = Gout + (size_t)N_GRAPHS * DIM;

    const int* src = ei;
    const int* dst = ei + N_EDGES;

    static bool attr_set = false;
    if (!attr_set) {
        cudaFuncSetAttribute(gemm_mma_kernel<1>, cudaFuncAttributeMaxDynamicSharedMemorySize, SMB_TOTAL);
        cudaFuncSetAttribute(gemm_mma_kernel<2>, cudaFuncAttributeMaxDynamicSharedMemorySize, SMB_TOTAL);
        attr_set = true;
    }

    const int nCopyBlocks    = (N_NODES * (DIM / 4)) / 256;      // 12500
    const int nScatterBlocks = (SCATTER_QTR + 255) / 256;        // 18750
    const int nGemmBlocks    = (N_NODES + 127) / 128;            // 782

    wprep_kernel<<<(6 * 4096 + 255) / 256, 256>>>(W1, W2);
    seg_bounds_kernel<<<(N_NODES + 256) / 256, 256>>>(batch);

    for (int i = 0; i < N_LAYERS; i++) {
        const float* Hin = (i == 0) ? x : Hout;
        if (i == 0) copy_to_agg_kernel<<<nCopyBlocks, 256>>>(Hin);
        scatter_add_kernel<<<nScatterBlocks, 256>>>(Hin, src, dst);
        gemm_mma_kernel<1><<<nGemmBlocks, 256, SMB_TOTAL>>>(i, b1 + i * DIM, nullptr, nullptr);
        gemm_mma_kernel<2><<<nGemmBlocks, 256, SMB_TOTAL>>>(i + 3, b2 + i * DIM,
                                                            g1 + i * DIM, bt1 + i * DIM);
        if (i + 1 < N_LAYERS)
            apply_relu_kernel<true><<<nCopyBlocks, 256>>>(Hout, g2 + i * DIM,
                                                          go + i * DIM, bo + i * DIM);
        else
            apply_relu_kernel<false><<<nCopyBlocks, 256>>>(Hout, g2 + i * DIM,
                                                           go + i * DIM, bo + i * DIM);
    }

    graph_fc_kernel<<<N_GRAPHS, 128>>>(Hout, fcW, fcb, Gout, Cout);
}